// round 7
// baseline (speedup 1.0000x reference)
#include <cuda_runtime.h>
#include <cuda_bf16.h>
#include <math.h>
#include <stdint.h>

#define THREADS 256
#define TM      128
#define KD      256
#define NN      64
#define KC      32
#define NCH     8

#define AS      40           // bf16 per A row (32 + 8 pad) -> 80 B
#define BS      264          // bf16 per B row (256 + 8 pad) -> 528 B
#define HSP     68
#define A_PLANE (TM * AS * 2)            // 10240 B
#define A_BUF   (2 * A_PLANE)            // 20480 B (hi+lo)

// smem byte offsets
#define OFF_B1  0
#define OFF_B2  256
#define OFF_CW  272
#define OFF_SW  336
#define OFF_W2T 400          // 256 f transposed -> ends 1424
#define OFF_A   1536         // 2 bufs x (hi,lo)
#define OFF_BH  (OFF_A + 2 * A_BUF)          // 42496
#define OFF_BL  (OFF_BH + NN * BS * 2)       // 76288
#define SMEM_BYTES (OFF_BL + NN * BS * 2)    // 110080
#define OFF_HS  OFF_A        // 128*68*4 = 34816 <= 40960

__device__ __forceinline__ void ldm_x4(uint32_t& r0, uint32_t& r1, uint32_t& r2, uint32_t& r3,
                                       uint32_t addr) {
    asm volatile("ldmatrix.sync.aligned.m8n8.x4.shared.b16 {%0,%1,%2,%3}, [%4];"
                 : "=r"(r0), "=r"(r1), "=r"(r2), "=r"(r3) : "r"(addr));
}
__device__ __forceinline__ void mma_bf16(float* c, const uint32_t* a, uint32_t b0, uint32_t b1) {
    asm volatile("mma.sync.aligned.m16n8k16.row.col.f32.bf16.bf16.f32 "
                 "{%0,%1,%2,%3}, {%4,%5,%6,%7}, {%8,%9}, {%0,%1,%2,%3};"
                 : "+f"(c[0]), "+f"(c[1]), "+f"(c[2]), "+f"(c[3])
                 : "r"(a[0]), "r"(a[1]), "r"(a[2]), "r"(a[3]), "r"(b0), "r"(b1));
}

extern "C" __global__ void __launch_bounds__(THREADS, 2)
qc_hmma3_kernel(const float* __restrict__ x,  const float* __restrict__ W1,
                const float* __restrict__ b1, const float* __restrict__ W2,
                const float* __restrict__ b2, const float* __restrict__ qw,
                float* __restrict__ out)
{
    extern __shared__ char sm[];
    const uint32_t sb = (uint32_t)__cvta_generic_to_shared(sm);
    const int t   = threadIdx.x;
    const int wid = t >> 5;
    const int lid = t & 31;
    const int wr  = wid >> 1;
    const int wc  = wid & 1;
    const long row0 = (long)blockIdx.x * TM;

    float* b1s = (float*)(sm + OFF_B1);
    float* b2s = (float*)(sm + OFF_B2);
    float* cw  = (float*)(sm + OFF_CW);
    float* sw  = (float*)(sm + OFF_SW);
    float* W2t = (float*)(sm + OFF_W2T);

    if (t < 64)  b1s[t] = b1[t];
    if (t < 4)   b2s[t] = b2[t];
    if (t < 16)  sincosf(0.5f * qw[t], &sw[t], &cw[t]);
    { int j = t >> 6, q = t & 63; W2t[q * 4 + j] = W2[t]; }

    // ---- W1 -> smem bf16 hi/lo ----
    #pragma unroll
    for (int i = 0; i < 16; ++i) {
        int idx = t + i * THREADS;
        int row = idx >> 6;
        int k4  = idx & 63;
        float4 v = *(const float4*)(W1 + row * KD + k4 * 4);
        __nv_bfloat162 h0 = __floats2bfloat162_rn(v.x, v.y);
        __nv_bfloat162 h1 = __floats2bfloat162_rn(v.z, v.w);
        __nv_bfloat162 l0 = __floats2bfloat162_rn(v.x - __bfloat162float(h0.x),
                                                  v.y - __bfloat162float(h0.y));
        __nv_bfloat162 l1 = __floats2bfloat162_rn(v.z - __bfloat162float(h1.x),
                                                  v.w - __bfloat162float(h1.y));
        uint32_t o = (uint32_t)row * (BS * 2) + (uint32_t)k4 * 8;
        *(uint2*)(sm + OFF_BH + o) = make_uint2(*(uint32_t*)&h0, *(uint32_t*)&h1);
        *(uint2*)(sm + OFF_BL + o) = make_uint2(*(uint32_t*)&l0, *(uint32_t*)&l1);
    }

    // per-thread x-slot: 4 float4 per chunk (128 rows x 8 slots)
    float4 xv[4];
    const float* xg = x + row0 * KD;
    const int xr  = t >> 1;                  // base row pair
    auto load_chunk = [&](int ch) {
        #pragma unroll
        for (int i = 0; i < 4; ++i) {
            int idx = t + i * THREADS;       // [0,1024)
            int r   = idx >> 3;
            int s4  = idx & 7;
            xv[i] = *(const float4*)(xg + r * KD + ch * KC + s4 * 4);
        }
    };
    auto store_part = [&](int buf, int half) {  // half 0: i=0,1; half 1: i=2,3
        #pragma unroll
        for (int i2 = 0; i2 < 2; ++i2) {
            int i   = half * 2 + i2;
            int idx = t + i * THREADS;
            int r   = idx >> 3;
            int s4  = idx & 7;
            float4 v = xv[i];
            __nv_bfloat162 h0 = __floats2bfloat162_rn(v.x, v.y);
            __nv_bfloat162 h1 = __floats2bfloat162_rn(v.z, v.w);
            __nv_bfloat162 l0 = __floats2bfloat162_rn(v.x - __bfloat162float(h0.x),
                                                      v.y - __bfloat162float(h0.y));
            __nv_bfloat162 l1 = __floats2bfloat162_rn(v.z - __bfloat162float(h1.x),
                                                      v.w - __bfloat162float(h1.y));
            uint32_t o = (uint32_t)buf * A_BUF + (uint32_t)r * (AS * 2) + (uint32_t)s4 * 8;
            *(uint2*)(sm + OFF_A + o)           = make_uint2(*(uint32_t*)&h0, *(uint32_t*)&h1);
            *(uint2*)(sm + OFF_A + o + A_PLANE) = make_uint2(*(uint32_t*)&l0, *(uint32_t*)&l1);
        }
    };
    (void)xr;

    load_chunk(0);
    store_part(0, 0);
    store_part(0, 1);
    __syncthreads();

    float acc[2][4][4];
    #pragma unroll
    for (int mi = 0; mi < 2; ++mi)
        #pragma unroll
        for (int ni = 0; ni < 4; ++ni)
            #pragma unroll
            for (int c = 0; c < 4; ++c) acc[mi][ni][c] = 0.0f;

    const uint32_t aRowOff = (uint32_t)(wr * 32 + (lid & 15)) * (AS * 2) + (uint32_t)(lid >> 4) * 16;
    const uint32_t bRow    = (uint32_t)(wc * 32 + ((lid >> 4) << 3) + (lid & 7));
    const uint32_t bKhalf  = (uint32_t)((lid >> 3) & 1) * 16;
    const uint32_t bOffBase = bRow * (BS * 2) + bKhalf;

    for (int ch = 0; ch < NCH; ++ch) {
        const int buf = ch & 1;
        const bool more = (ch + 1 < NCH);
        if (more) load_chunk(ch + 1);

        const uint32_t aHb = sb + OFF_A + buf * A_BUF + aRowOff;
        const uint32_t aLb = aHb + A_PLANE;
        const uint32_t bHb = sb + OFF_BH + bOffBase + (uint32_t)ch * KC * 2;
        const uint32_t bLb = sb + OFF_BL + bOffBase + (uint32_t)ch * KC * 2;

        #pragma unroll
        for (int ks = 0; ks < 2; ++ks) {
            uint32_t ah0[4], ah1[4], al0[4], al1[4];
            uint32_t bh0[4], bh1[4], bl0[4], bl1[4];
            ldm_x4(ah0[0], ah0[1], ah0[2], ah0[3], aHb + ks * 32);
            ldm_x4(ah1[0], ah1[1], ah1[2], ah1[3], aHb + ks * 32 + 16 * (AS * 2));
            ldm_x4(al0[0], al0[1], al0[2], al0[3], aLb + ks * 32);
            ldm_x4(al1[0], al1[1], al1[2], al1[3], aLb + ks * 32 + 16 * (AS * 2));
            ldm_x4(bh0[0], bh0[1], bh0[2], bh0[3], bHb + ks * 32);
            ldm_x4(bh1[0], bh1[1], bh1[2], bh1[3], bHb + ks * 32 + 16 * (BS * 2));
            ldm_x4(bl0[0], bl0[1], bl0[2], bl0[3], bLb + ks * 32);
            ldm_x4(bl1[0], bl1[1], bl1[2], bl1[3], bLb + ks * 32 + 16 * (BS * 2));

            // fill ldmatrix->MMA latency with next chunk's convert+store
            if (more) store_part(buf ^ 1, ks);

            #pragma unroll
            for (int ni = 0; ni < 4; ++ni) {
                uint32_t hb0 = (ni < 2) ? bh0[(ni & 1) * 2]     : bh1[(ni & 1) * 2];
                uint32_t hb1 = (ni < 2) ? bh0[(ni & 1) * 2 + 1] : bh1[(ni & 1) * 2 + 1];
                uint32_t lb0 = (ni < 2) ? bl0[(ni & 1) * 2]     : bl1[(ni & 1) * 2];
                uint32_t lb1 = (ni < 2) ? bl0[(ni & 1) * 2 + 1] : bl1[(ni & 1) * 2 + 1];
                mma_bf16(acc[0][ni], ah0, hb0, hb1);
                mma_bf16(acc[1][ni], ah1, hb0, hb1);
                mma_bf16(acc[0][ni], ah0, lb0, lb1);
                mma_bf16(acc[1][ni], ah1, lb0, lb1);
                mma_bf16(acc[0][ni], al0, hb0, hb1);
                mma_bf16(acc[1][ni], al1, hb0, hb1);
            }
        }
        __syncthreads();
    }

    // ---- stage H tile in smem (reuses A region) ----
    float* Hs = (float*)(sm + OFF_HS);
    {
        #pragma unroll
        for (int mi = 0; mi < 2; ++mi)
            #pragma unroll
            for (int ni = 0; ni < 4; ++ni) {
                int row = wr * 32 + mi * 16 + (lid >> 2);
                int col = wc * 32 + ni * 8 + (lid & 3) * 2;
                *(float2*)&Hs[row * HSP + col]       = make_float2(acc[mi][ni][0], acc[mi][ni][1]);
                *(float2*)&Hs[(row + 8) * HSP + col] = make_float2(acc[mi][ni][2], acc[mi][ni][3]);
            }
    }
    __syncthreads();

    // ---- per-row epilogue ----
    if (t < TM) {
        float ang0 = b2s[0], ang1 = b2s[1], ang2 = b2s[2], ang3 = b2s[3];
        #pragma unroll
        for (int q4 = 0; q4 < 16; ++q4) {
            float4 h4 = *(const float4*)(Hs + t * HSP + q4 * 4);
            float4 bb = *(const float4*)(b1s + q4 * 4);
            #pragma unroll
            for (int i = 0; i < 4; ++i) {
                float hv = (i == 0) ? h4.x : (i == 1) ? h4.y : (i == 2) ? h4.z : h4.w;
                float bv = (i == 0) ? bb.x : (i == 1) ? bb.y : (i == 2) ? bb.z : bb.w;
                float hq = fmaxf(hv + bv, 0.0f);
                float4 w = *(const float4*)(W2t + (q4 * 4 + i) * 4);
                ang0 += hq * w.x;  ang1 += hq * w.y;
                ang2 += hq * w.z;  ang3 += hq * w.w;
            }
        }
        float ang[4] = { tanhf(ang0), tanhf(ang1), tanhf(ang2), tanhf(ang3) };

        float sr[16], si[16];
        #pragma unroll
        for (int i = 0; i < 16; ++i) { sr[i] = 0.0f; si[i] = 0.0f; }
        sr[0] = 1.0f;

        #pragma unroll
        for (int w = 0; w < 4; ++w) {
            float c, s;
            __sincosf(0.5f * ang[w], &s, &c);
            const int m = 8 >> w;
            #pragma unroll
            for (int i0 = 0; i0 < 16; ++i0) if (!(i0 & m)) {
                const int i1 = i0 | m;
                float r0 = sr[i0], r1 = sr[i1];
                sr[i0] = c * r0 - s * r1;  sr[i1] = s * r0 + c * r1;
                float q0 = si[i0], q1 = si[i1];
                si[i0] = c * q0 - s * q1;  si[i1] = s * q0 + c * q1;
            }
        }

        #pragma unroll
        for (int l = 0; l < 2; ++l) {
            #pragma unroll
            for (int i = 0; i < 4; ++i) {
                {
                    const float c = cw[l * 8 + i * 2], s = sw[l * 8 + i * 2];
                    const int m = 8 >> i;
                    #pragma unroll
                    for (int i0 = 0; i0 < 16; ++i0) if (!(i0 & m)) {
                        const int i1 = i0 | m;
                        float r0 = sr[i0], r1 = sr[i1];
                        sr[i0] = c * r0 - s * r1;  sr[i1] = s * r0 + c * r1;
                        float q0 = si[i0], q1 = si[i1];
                        si[i0] = c * q0 - s * q1;  si[i1] = s * q0 + c * q1;
                    }
                }
                {
                    const float c = cw[l * 8 + i * 2 + 1], s = sw[l * 8 + i * 2 + 1];
                    const int m = 8 >> i;
                    #pragma unroll
                    for (int idx = 0; idx < 16; ++idx) {
                        float re = sr[idx], im = si[idx];
                        if (idx & m) { sr[idx] = re * c - im * s;  si[idx] = im * c + re * s; }
                        else         { sr[idx] = re * c + im * s;  si[idx] = im * c - re * s; }
                    }
                }
            }
            #pragma unroll
            for (int cix = 0; cix < 4; ++cix) {
                const int ctrl = cix, tgt = (cix + 1) & 3;
                const int mc = 8 >> ctrl, mt = 8 >> tgt;
                #pragma unroll
                for (int idx = 0; idx < 16; ++idx)
                    if ((idx & mc) && !(idx & mt)) {
                        const int j2 = idx | mt;
                        float tr = sr[idx]; sr[idx] = sr[j2]; sr[j2] = tr;
                        float ti = si[idx]; si[idx] = si[j2]; si[j2] = ti;
                    }
            }
        }

        float z = 0.0f;
        #pragma unroll
        for (int idx = 0; idx < 16; ++idx) {
            float p = sr[idx] * sr[idx] + si[idx] * si[idx];
            z += (idx & 8) ? -p : p;
        }
        out[row0 + t] = z;
    }
}

extern "C" void kernel_launch(void* const* d_in, const int* in_sizes, int n_in,
                              void* d_out, int out_size) {
    const float* x  = (const float*)d_in[0];
    const float* W1 = (const float*)d_in[1];
    const float* b1 = (const float*)d_in[2];
    const float* W2 = (const float*)d_in[3];
    const float* b2 = (const float*)d_in[4];
    const float* qw = (const float*)d_in[5];
    float* out = (float*)d_out;

    const int B = in_sizes[0] / KD;   // 65536
    cudaFuncSetAttribute(qc_hmma3_kernel,
                         cudaFuncAttributeMaxDynamicSharedMemorySize, SMEM_BYTES);
    qc_hmma3_kernel<<<B / TM, THREADS, SMEM_BYTES>>>(x, W1, b1, W2, b2, qw, out);
}

// round 8
// speedup vs baseline: 1.2173x; 1.2173x over previous
#include <cuda_runtime.h>
#include <cuda_fp16.h>
#include <math.h>
#include <stdint.h>

#define THREADS 256
#define TM      128
#define KD      256
#define NN      64
#define KC      64
#define NCH     4

#define AS      72           // fp16 per A row (64 + 8 pad) -> 144 B
#define BS      264          // fp16 per B row (256 + 8 pad) -> 528 B
#define HSP     68
#define A_PLANE (TM * AS * 2)            // 18432 B (single fp16 plane)

// smem byte offsets
#define OFF_B1  0
#define OFF_B2  256
#define OFF_CW  272
#define OFF_SW  336
#define OFF_W2T 400          // 256 f transposed -> ends 1424
#define OFF_A   1536         // 2 buffers, single plane each
#define OFF_BH  (OFF_A + 2 * A_PLANE)        // 38400
#define OFF_BL  (OFF_BH + NN * BS * 2)       // 72192
#define SMEM_BYTES (OFF_BL + NN * BS * 2)    // 105984
#define OFF_HS  OFF_A        // 128*68*4 = 34816 <= 36864

__device__ __forceinline__ void ldm_x4(uint32_t& r0, uint32_t& r1, uint32_t& r2, uint32_t& r3,
                                       uint32_t addr) {
    asm volatile("ldmatrix.sync.aligned.m8n8.x4.shared.b16 {%0,%1,%2,%3}, [%4];"
                 : "=r"(r0), "=r"(r1), "=r"(r2), "=r"(r3) : "r"(addr));
}
__device__ __forceinline__ void mma_f16(float* c, const uint32_t* a, uint32_t b0, uint32_t b1) {
    asm volatile("mma.sync.aligned.m16n8k16.row.col.f32.f16.f16.f32 "
                 "{%0,%1,%2,%3}, {%4,%5,%6,%7}, {%8,%9}, {%0,%1,%2,%3};"
                 : "+f"(c[0]), "+f"(c[1]), "+f"(c[2]), "+f"(c[3])
                 : "r"(a[0]), "r"(a[1]), "r"(a[2]), "r"(a[3]), "r"(b0), "r"(b1));
}

extern "C" __global__ void __launch_bounds__(THREADS, 2)
qc_hmma4_kernel(const float* __restrict__ x,  const float* __restrict__ W1,
                const float* __restrict__ b1, const float* __restrict__ W2,
                const float* __restrict__ b2, const float* __restrict__ qw,
                float* __restrict__ out)
{
    extern __shared__ char sm[];
    const uint32_t sb = (uint32_t)__cvta_generic_to_shared(sm);
    const int t   = threadIdx.x;
    const int wid = t >> 5;
    const int lid = t & 31;
    const int wr  = wid >> 1;
    const int wc  = wid & 1;
    const long row0 = (long)blockIdx.x * TM;

    float* b1s = (float*)(sm + OFF_B1);
    float* b2s = (float*)(sm + OFF_B2);
    float* cw  = (float*)(sm + OFF_CW);
    float* sw  = (float*)(sm + OFF_SW);
    float* W2t = (float*)(sm + OFF_W2T);

    if (t < 64)  b1s[t] = b1[t];
    if (t < 4)   b2s[t] = b2[t];
    if (t < 16)  sincosf(0.5f * qw[t], &sw[t], &cw[t]);
    { int j = t >> 6, q = t & 63; W2t[q * 4 + j] = W2[t]; }

    // ---- W1 -> smem fp16 hi/lo (exact split: W = Wh + Wl to ~2^-22) ----
    #pragma unroll
    for (int i = 0; i < 16; ++i) {
        int idx = t + i * THREADS;
        int row = idx >> 6;
        int k4  = idx & 63;
        float4 v = *(const float4*)(W1 + row * KD + k4 * 4);
        __half2 h0 = __floats2half2_rn(v.x, v.y);
        __half2 h1 = __floats2half2_rn(v.z, v.w);
        __half2 l0 = __floats2half2_rn(v.x - __half2float(h0.x),
                                       v.y - __half2float(h0.y));
        __half2 l1 = __floats2half2_rn(v.z - __half2float(h1.x),
                                       v.w - __half2float(h1.y));
        uint32_t o = (uint32_t)row * (BS * 2) + (uint32_t)k4 * 8;
        *(uint2*)(sm + OFF_BH + o) = make_uint2(*(uint32_t*)&h0, *(uint32_t*)&h1);
        *(uint2*)(sm + OFF_BL + o) = make_uint2(*(uint32_t*)&l0, *(uint32_t*)&l1);
    }

    // ---- x chunk: load fp32 to regs, convert to single fp16 plane ----
    float4 xv[8];
    const float* xg = x + row0 * KD;
    auto load_chunk = [&](int ch) {
        #pragma unroll
        for (int i = 0; i < 8; ++i) {
            int idx = t + i * THREADS;      // [0,2048)
            int r   = idx >> 4;
            int s4  = idx & 15;
            xv[i] = *(const float4*)(xg + r * KD + ch * KC + s4 * 4);
        }
    };
    auto store_chunk = [&](int buf) {
        #pragma unroll
        for (int i = 0; i < 8; ++i) {
            int idx = t + i * THREADS;
            int r   = idx >> 4;
            int s4  = idx & 15;
            float4 v = xv[i];
            __half2 h0 = __floats2half2_rn(v.x, v.y);
            __half2 h1 = __floats2half2_rn(v.z, v.w);
            uint32_t o = (uint32_t)buf * A_PLANE + (uint32_t)r * (AS * 2) + (uint32_t)s4 * 8;
            *(uint2*)(sm + OFF_A + o) = make_uint2(*(uint32_t*)&h0, *(uint32_t*)&h1);
        }
    };

    load_chunk(0);
    store_chunk(0);
    __syncthreads();

    float acc[2][4][4];
    #pragma unroll
    for (int mi = 0; mi < 2; ++mi)
        #pragma unroll
        for (int ni = 0; ni < 4; ++ni)
            #pragma unroll
            for (int c = 0; c < 4; ++c) acc[mi][ni][c] = 0.0f;

    const uint32_t aRowOff = (uint32_t)(wr * 32 + (lid & 15)) * (AS * 2) + (uint32_t)(lid >> 4) * 16;
    const uint32_t bRow    = (uint32_t)(wc * 32 + ((lid >> 4) << 3) + (lid & 7));
    const uint32_t bKhalf  = (uint32_t)((lid >> 3) & 1) * 16;
    const uint32_t bOffBase = bRow * (BS * 2) + bKhalf;

    for (int ch = 0; ch < NCH; ++ch) {
        const int buf = ch & 1;
        const bool more = (ch + 1 < NCH);
        if (more) load_chunk(ch + 1);

        const uint32_t aB  = sb + OFF_A + buf * A_PLANE + aRowOff;
        const uint32_t bHb = sb + OFF_BH + bOffBase + (uint32_t)ch * KC * 2;
        const uint32_t bLb = sb + OFF_BL + bOffBase + (uint32_t)ch * KC * 2;

        #pragma unroll
        for (int ks = 0; ks < 4; ++ks) {
            uint32_t a0[4], a1[4];
            uint32_t bh0[4], bh1[4], bl0[4], bl1[4];
            ldm_x4(a0[0], a0[1], a0[2], a0[3], aB + ks * 32);
            ldm_x4(a1[0], a1[1], a1[2], a1[3], aB + ks * 32 + 16 * (AS * 2));
            ldm_x4(bh0[0], bh0[1], bh0[2], bh0[3], bHb + ks * 32);
            ldm_x4(bh1[0], bh1[1], bh1[2], bh1[3], bHb + ks * 32 + 16 * (BS * 2));
            ldm_x4(bl0[0], bl0[1], bl0[2], bl0[3], bLb + ks * 32);
            ldm_x4(bl1[0], bl1[1], bl1[2], bl1[3], bLb + ks * 32 + 16 * (BS * 2));

            #pragma unroll
            for (int ni = 0; ni < 4; ++ni) {
                uint32_t hb0 = (ni < 2) ? bh0[(ni & 1) * 2]     : bh1[(ni & 1) * 2];
                uint32_t hb1 = (ni < 2) ? bh0[(ni & 1) * 2 + 1] : bh1[(ni & 1) * 2 + 1];
                uint32_t lb0 = (ni < 2) ? bl0[(ni & 1) * 2]     : bl1[(ni & 1) * 2];
                uint32_t lb1 = (ni < 2) ? bl0[(ni & 1) * 2 + 1] : bl1[(ni & 1) * 2 + 1];
                mma_f16(acc[0][ni], a0, hb0, hb1);   // A*Bh
                mma_f16(acc[1][ni], a1, hb0, hb1);
                mma_f16(acc[0][ni], a0, lb0, lb1);   // A*Bl
                mma_f16(acc[1][ni], a1, lb0, lb1);
            }
        }

        if (more) store_chunk(buf ^ 1);   // other buffer: fully consumed last iter
        __syncthreads();
    }

    // ---- stage H tile in smem (reuses A region) ----
    float* Hs = (float*)(sm + OFF_HS);
    {
        #pragma unroll
        for (int mi = 0; mi < 2; ++mi)
            #pragma unroll
            for (int ni = 0; ni < 4; ++ni) {
                int row = wr * 32 + mi * 16 + (lid >> 2);
                int col = wc * 32 + ni * 8 + (lid & 3) * 2;
                *(float2*)&Hs[row * HSP + col]       = make_float2(acc[mi][ni][0], acc[mi][ni][1]);
                *(float2*)&Hs[(row + 8) * HSP + col] = make_float2(acc[mi][ni][2], acc[mi][ni][3]);
            }
    }
    __syncthreads();

    // ---- per-row epilogue ----
    if (t < TM) {
        float ang0 = b2s[0], ang1 = b2s[1], ang2 = b2s[2], ang3 = b2s[3];
        #pragma unroll
        for (int q4 = 0; q4 < 16; ++q4) {
            float4 h4 = *(const float4*)(Hs + t * HSP + q4 * 4);
            float4 bb = *(const float4*)(b1s + q4 * 4);
            #pragma unroll
            for (int i = 0; i < 4; ++i) {
                float hv = (i == 0) ? h4.x : (i == 1) ? h4.y : (i == 2) ? h4.z : h4.w;
                float bv = (i == 0) ? bb.x : (i == 1) ? bb.y : (i == 2) ? bb.z : bb.w;
                float hq = fmaxf(hv + bv, 0.0f);
                float4 w = *(const float4*)(W2t + (q4 * 4 + i) * 4);
                ang0 += hq * w.x;  ang1 += hq * w.y;
                ang2 += hq * w.z;  ang3 += hq * w.w;
            }
        }
        float ang[4] = { tanhf(ang0), tanhf(ang1), tanhf(ang2), tanhf(ang3) };

        float sr[16], si[16];
        #pragma unroll
        for (int i = 0; i < 16; ++i) { sr[i] = 0.0f; si[i] = 0.0f; }
        sr[0] = 1.0f;

        #pragma unroll
        for (int w = 0; w < 4; ++w) {
            float c, s;
            __sincosf(0.5f * ang[w], &s, &c);
            const int m = 8 >> w;
            #pragma unroll
            for (int i0 = 0; i0 < 16; ++i0) if (!(i0 & m)) {
                const int i1 = i0 | m;
                float r0 = sr[i0], r1 = sr[i1];
                sr[i0] = c * r0 - s * r1;  sr[i1] = s * r0 + c * r1;
                float q0 = si[i0], q1 = si[i1];
                si[i0] = c * q0 - s * q1;  si[i1] = s * q0 + c * q1;
            }
        }

        #pragma unroll
        for (int l = 0; l < 2; ++l) {
            #pragma unroll
            for (int i = 0; i < 4; ++i) {
                {   // RY(weights[l,i,0])
                    const float c = cw[l * 8 + i * 2], s = sw[l * 8 + i * 2];
                    const int m = 8 >> i;
                    #pragma unroll
                    for (int i0 = 0; i0 < 16; ++i0) if (!(i0 & m)) {
                        const int i1 = i0 | m;
                        float r0 = sr[i0], r1 = sr[i1];
                        sr[i0] = c * r0 - s * r1;  sr[i1] = s * r0 + c * r1;
                        float q0 = si[i0], q1 = si[i1];
                        si[i0] = c * q0 - s * q1;  si[i1] = s * q0 + c * q1;
                    }
                }
                {   // RZ(weights[l,i,1])
                    const float c = cw[l * 8 + i * 2 + 1], s = sw[l * 8 + i * 2 + 1];
                    const int m = 8 >> i;
                    #pragma unroll
                    for (int idx = 0; idx < 16; ++idx) {
                        float re = sr[idx], im = si[idx];
                        if (idx & m) { sr[idx] = re * c - im * s;  si[idx] = im * c + re * s; }
                        else         { sr[idx] = re * c + im * s;  si[idx] = im * c - re * s; }
                    }
                }
            }
            #pragma unroll
            for (int cix = 0; cix < 4; ++cix) {
                const int ctrl = cix, tgt = (cix + 1) & 3;
                const int mc = 8 >> ctrl, mt = 8 >> tgt;
                #pragma unroll
                for (int idx = 0; idx < 16; ++idx)
                    if ((idx & mc) && !(idx & mt)) {
                        const int j2 = idx | mt;
                        float tr = sr[idx]; sr[idx] = sr[j2]; sr[j2] = tr;
                        float ti = si[idx]; si[idx] = si[j2]; si[j2] = ti;
                    }
            }
        }

        float z = 0.0f;
        #pragma unroll
        for (int idx = 0; idx < 16; ++idx) {
            float p = sr[idx] * sr[idx] + si[idx] * si[idx];
            z += (idx & 8) ? -p : p;
        }
        out[row0 + t] = z;
    }
}

extern "C" void kernel_launch(void* const* d_in, const int* in_sizes, int n_in,
                              void* d_out, int out_size) {
    const float* x  = (const float*)d_in[0];
    const float* W1 = (const float*)d_in[1];
    const float* b1 = (const float*)d_in[2];
    const float* W2 = (const float*)d_in[3];
    const float* b2 = (const float*)d_in[4];
    const float* qw = (const float*)d_in[5];
    float* out = (float*)d_out;

    const int B = in_sizes[0] / KD;   // 65536
    cudaFuncSetAttribute(qc_hmma4_kernel,
                         cudaFuncAttributeMaxDynamicSharedMemorySize, SMEM_BYTES);
    qc_hmma4_kernel<<<B / TM, THREADS, SMEM_BYTES>>>(x, W1, b1, W2, b2, qw, out);
}

// round 9
// speedup vs baseline: 1.4492x; 1.1905x over previous
#include <cuda_runtime.h>
#include <cuda_fp16.h>
#include <math.h>
#include <stdint.h>

#define THREADS 256
#define TM      128
#define KD      256
#define NN      64
#define KC      32
#define NCH     8

#define AS      40           // fp16 per A row (32 + 8 pad) -> 80 B
#define BS      264          // fp16 per B row (256 + 8 pad) -> 528 B
#define HSP     68
#define A_PLANE (TM * AS * 2)            // 10240 B

// smem byte offsets
#define OFF_B1  0
#define OFF_B2  256
#define OFF_CW  272
#define OFF_SW  336
#define OFF_W2T 400          // 256 f transposed -> ends 1424
#define OFF_A   1536         // 2 buffers
#define OFF_B   (OFF_A + 2 * A_PLANE)        // 22016
#define SMEM_BYTES (OFF_B + NN * BS * 2)     // 55808
#define OFF_HS  OFF_A        // 128*68*4 = 34816 <= 54272 (A+B dead after GEMM)

__device__ __forceinline__ void ldm_x4(uint32_t& r0, uint32_t& r1, uint32_t& r2, uint32_t& r3,
                                       uint32_t addr) {
    asm volatile("ldmatrix.sync.aligned.m8n8.x4.shared.b16 {%0,%1,%2,%3}, [%4];"
                 : "=r"(r0), "=r"(r1), "=r"(r2), "=r"(r3) : "r"(addr));
}
__device__ __forceinline__ void mma_f16(float* c, const uint32_t* a, uint32_t b0, uint32_t b1) {
    asm volatile("mma.sync.aligned.m16n8k16.row.col.f32.f16.f16.f32 "
                 "{%0,%1,%2,%3}, {%4,%5,%6,%7}, {%8,%9}, {%0,%1,%2,%3};"
                 : "+f"(c[0]), "+f"(c[1]), "+f"(c[2]), "+f"(c[3])
                 : "r"(a[0]), "r"(a[1]), "r"(a[2]), "r"(a[3]), "r"(b0), "r"(b1));
}

extern "C" __global__ void __launch_bounds__(THREADS, 3)
qc_hmma5_kernel(const float* __restrict__ x,  const float* __restrict__ W1,
                const float* __restrict__ b1, const float* __restrict__ W2,
                const float* __restrict__ b2, const float* __restrict__ qw,
                float* __restrict__ out)
{
    extern __shared__ char sm[];
    const uint32_t sb = (uint32_t)__cvta_generic_to_shared(sm);
    const int t   = threadIdx.x;
    const int wid = t >> 5;
    const int lid = t & 31;
    const int wr  = wid >> 1;
    const int wc  = wid & 1;
    const long row0 = (long)blockIdx.x * TM;

    float* b1s = (float*)(sm + OFF_B1);
    float* b2s = (float*)(sm + OFF_B2);
    float* cw  = (float*)(sm + OFF_CW);
    float* sw  = (float*)(sm + OFF_SW);
    float* W2t = (float*)(sm + OFF_W2T);

    if (t < 64)  b1s[t] = b1[t];
    if (t < 4)   b2s[t] = b2[t];
    if (t < 16)  sincosf(0.5f * qw[t], &sw[t], &cw[t]);
    { int j = t >> 6, q = t & 63; W2t[q * 4 + j] = W2[t]; }

    // ---- W1 -> smem fp16 (single plane) ----
    #pragma unroll
    for (int i = 0; i < 16; ++i) {
        int idx = t + i * THREADS;
        int row = idx >> 6;
        int k4  = idx & 63;
        float4 v = *(const float4*)(W1 + row * KD + k4 * 4);
        __half2 h0 = __floats2half2_rn(v.x, v.y);
        __half2 h1 = __floats2half2_rn(v.z, v.w);
        uint32_t o = (uint32_t)row * (BS * 2) + (uint32_t)k4 * 8;
        *(uint2*)(sm + OFF_B + o) = make_uint2(*(uint32_t*)&h0, *(uint32_t*)&h1);
    }

    // ---- x chunk staging (4 float4 per thread) ----
    float4 xv[4];
    const float* xg = x + row0 * KD;
    auto load_chunk = [&](int ch) {
        #pragma unroll
        for (int i = 0; i < 4; ++i) {
            int idx = t + i * THREADS;      // [0,1024)
            int r   = idx >> 3;
            int s4  = idx & 7;
            xv[i] = *(const float4*)(xg + r * KD + ch * KC + s4 * 4);
        }
    };
    auto store_chunk = [&](int buf) {
        #pragma unroll
        for (int i = 0; i < 4; ++i) {
            int idx = t + i * THREADS;
            int r   = idx >> 3;
            int s4  = idx & 7;
            float4 v = xv[i];
            __half2 h0 = __floats2half2_rn(v.x, v.y);
            __half2 h1 = __floats2half2_rn(v.z, v.w);
            uint32_t o = (uint32_t)buf * A_PLANE + (uint32_t)r * (AS * 2) + (uint32_t)s4 * 8;
            *(uint2*)(sm + OFF_A + o) = make_uint2(*(uint32_t*)&h0, *(uint32_t*)&h1);
        }
    };

    load_chunk(0);
    store_chunk(0);
    __syncthreads();

    float acc[2][4][4];
    #pragma unroll
    for (int mi = 0; mi < 2; ++mi)
        #pragma unroll
        for (int ni = 0; ni < 4; ++ni)
            #pragma unroll
            for (int c = 0; c < 4; ++c) acc[mi][ni][c] = 0.0f;

    const uint32_t aRowOff = (uint32_t)(wr * 32 + (lid & 15)) * (AS * 2) + (uint32_t)(lid >> 4) * 16;
    const uint32_t bRow    = (uint32_t)(wc * 32 + ((lid >> 4) << 3) + (lid & 7));
    const uint32_t bKhalf  = (uint32_t)((lid >> 3) & 1) * 16;
    const uint32_t bOffBase = bRow * (BS * 2) + bKhalf;

    for (int ch = 0; ch < NCH; ++ch) {
        const int buf = ch & 1;
        const bool more = (ch + 1 < NCH);
        if (more) load_chunk(ch + 1);

        const uint32_t aB = sb + OFF_A + buf * A_PLANE + aRowOff;
        const uint32_t bB = sb + OFF_B + bOffBase + (uint32_t)ch * KC * 2;

        #pragma unroll
        for (int ks = 0; ks < 2; ++ks) {
            uint32_t a0[4], a1[4], b0[4], b1r[4];
            ldm_x4(a0[0], a0[1], a0[2], a0[3], aB + ks * 32);
            ldm_x4(a1[0], a1[1], a1[2], a1[3], aB + ks * 32 + 16 * (AS * 2));
            ldm_x4(b0[0], b0[1], b0[2], b0[3], bB + ks * 32);
            ldm_x4(b1r[0], b1r[1], b1r[2], b1r[3], bB + ks * 32 + 16 * (BS * 2));

            #pragma unroll
            for (int ni = 0; ni < 4; ++ni) {
                uint32_t rb0 = (ni < 2) ? b0[(ni & 1) * 2]     : b1r[(ni & 1) * 2];
                uint32_t rb1 = (ni < 2) ? b0[(ni & 1) * 2 + 1] : b1r[(ni & 1) * 2 + 1];
                mma_f16(acc[0][ni], a0, rb0, rb1);
                mma_f16(acc[1][ni], a1, rb0, rb1);
            }
        }

        if (more) store_chunk(buf ^ 1);
        __syncthreads();
    }

    // ---- stage H tile in smem ----
    float* Hs = (float*)(sm + OFF_HS);
    {
        #pragma unroll
        for (int mi = 0; mi < 2; ++mi)
            #pragma unroll
            for (int ni = 0; ni < 4; ++ni) {
                int row = wr * 32 + mi * 16 + (lid >> 2);
                int col = wc * 32 + ni * 8 + (lid & 3) * 2;
                *(float2*)&Hs[row * HSP + col]       = make_float2(acc[mi][ni][0], acc[mi][ni][1]);
                *(float2*)&Hs[(row + 8) * HSP + col] = make_float2(acc[mi][ni][2], acc[mi][ni][3]);
            }
    }
    __syncthreads();

    // ---- per-row epilogue ----
    if (t < TM) {
        float ang0 = b2s[0], ang1 = b2s[1], ang2 = b2s[2], ang3 = b2s[3];
        #pragma unroll
        for (int q4 = 0; q4 < 16; ++q4) {
            float4 h4 = *(const float4*)(Hs + t * HSP + q4 * 4);
            float4 bb = *(const float4*)(b1s + q4 * 4);
            #pragma unroll
            for (int i = 0; i < 4; ++i) {
                float hv = (i == 0) ? h4.x : (i == 1) ? h4.y : (i == 2) ? h4.z : h4.w;
                float bv = (i == 0) ? bb.x : (i == 1) ? bb.y : (i == 2) ? bb.z : bb.w;
                float hq = fmaxf(hv + bv, 0.0f);
                float4 w = *(const float4*)(W2t + (q4 * 4 + i) * 4);
                ang0 += hq * w.x;  ang1 += hq * w.y;
                ang2 += hq * w.z;  ang3 += hq * w.w;
            }
        }
        float ang[4] = { tanhf(ang0), tanhf(ang1), tanhf(ang2), tanhf(ang3) };

        float sr[16], si[16];
        #pragma unroll
        for (int i = 0; i < 16; ++i) { sr[i] = 0.0f; si[i] = 0.0f; }
        sr[0] = 1.0f;

        #pragma unroll
        for (int w = 0; w < 4; ++w) {
            float c, s;
            __sincosf(0.5f * ang[w], &s, &c);
            const int m = 8 >> w;
            #pragma unroll
            for (int i0 = 0; i0 < 16; ++i0) if (!(i0 & m)) {
                const int i1 = i0 | m;
                float r0 = sr[i0], r1 = sr[i1];
                sr[i0] = c * r0 - s * r1;  sr[i1] = s * r0 + c * r1;
                float q0 = si[i0], q1 = si[i1];
                si[i0] = c * q0 - s * q1;  si[i1] = s * q0 + c * q1;
            }
        }

        #pragma unroll
        for (int l = 0; l < 2; ++l) {
            #pragma unroll
            for (int i = 0; i < 4; ++i) {
                {   // RY(weights[l,i,0])
                    const float c = cw[l * 8 + i * 2], s = sw[l * 8 + i * 2];
                    const int m = 8 >> i;
                    #pragma unroll
                    for (int i0 = 0; i0 < 16; ++i0) if (!(i0 & m)) {
                        const int i1 = i0 | m;
                        float r0 = sr[i0], r1 = sr[i1];
                        sr[i0] = c * r0 - s * r1;  sr[i1] = s * r0 + c * r1;
                        float q0 = si[i0], q1 = si[i1];
                        si[i0] = c * q0 - s * q1;  si[i1] = s * q0 + c * q1;
                    }
                }
                {   // RZ(weights[l,i,1])
                    const float c = cw[l * 8 + i * 2 + 1], s = sw[l * 8 + i * 2 + 1];
                    const int m = 8 >> i;
                    #pragma unroll
                    for (int idx = 0; idx < 16; ++idx) {
                        float re = sr[idx], im = si[idx];
                        if (idx & m) { sr[idx] = re * c - im * s;  si[idx] = im * c + re * s; }
                        else         { sr[idx] = re * c + im * s;  si[idx] = im * c - re * s; }
                    }
                }
            }
            #pragma unroll
            for (int cix = 0; cix < 4; ++cix) {
                const int ctrl = cix, tgt = (cix + 1) & 3;
                const int mc = 8 >> ctrl, mt = 8 >> tgt;
                #pragma unroll
                for (int idx = 0; idx < 16; ++idx)
                    if ((idx & mc) && !(idx & mt)) {
                        const int j2 = idx | mt;
                        float tr = sr[idx]; sr[idx] = sr[j2]; sr[j2] = tr;
                        float ti = si[idx]; si[idx] = si[j2]; si[j2] = ti;
                    }
            }
        }

        float z = 0.0f;
        #pragma unroll
        for (int idx = 0; idx < 16; ++idx) {
            float p = sr[idx] * sr[idx] + si[idx] * si[idx];
            z += (idx & 8) ? -p : p;
        }
        out[row0 + t] = z;
    }
}

extern "C" void kernel_launch(void* const* d_in, const int* in_sizes, int n_in,
                              void* d_out, int out_size) {
    const float* x  = (const float*)d_in[0];
    const float* W1 = (const float*)d_in[1];
    const float* b1 = (const float*)d_in[2];
    const float* W2 = (const float*)d_in[3];
    const float* b2 = (const float*)d_in[4];
    const float* qw = (const float*)d_in[5];
    float* out = (float*)d_out;

    const int B = in_sizes[0] / KD;   // 65536
    cudaFuncSetAttribute(qc_hmma5_kernel,
                         cudaFuncAttributeMaxDynamicSharedMemorySize, SMEM_BYTES);
    qc_hmma5_kernel<<<B / TM, THREADS, SMEM_BYTES>>>(x, W1, b1, W2, b2, qw, out);
}